// round 13
// baseline (speedup 1.0000x reference)
#include <cuda_runtime.h>
#include <math.h>
#include <stdint.h>

// Problem constants
#define NS     8
#define NB     256
#define NT     512
#define OBS    128
#define HID    512
#define XD     64
#define SB     2048        // NS*NB
#define THREADS 512
#define NBLK   128
#define ROWS   16          // rows per block: 2 b's x 8 samples
#define KTOT   144         // (HID + XD)/4 float4-chunks of K

#define LOG2PI 1.8378770664093453f

typedef unsigned long long u64;

// ---- weights reorganized for streaming ----
// g_Wc[kq][c] : float4 over k; kq<128 -> W_hh (K=512), kq in [128,144) -> W_ih l-part (K=64)
//               c = gate*512 + j, gate 0=r,1=z,2=n
__device__ float4 g_Wc[KTOT * 1536];
// g_Wy[kq][c] : float4 over k (y-part of W_ih, K=128)
__device__ float4 g_Wy[32 * 1536];
// g_Woq[kq][c]: float4 over k (K=512), c in [0,128): loc(64) | scale(64)
__device__ float4 g_Woq[128 * 128];
__device__ float g_bR[512], g_bZ[512], g_bIN[512], g_bHN[512], g_bO[128];

__global__ void prep_kernel(const float* __restrict__ W_ih, const float* __restrict__ W_hh,
                            const float* __restrict__ b_ih, const float* __restrict__ b_hh,
                            const float* __restrict__ W_loc, const float* __restrict__ b_loc,
                            const float* __restrict__ W_scale, const float* __restrict__ b_scale) {
    int idx = blockIdx.x * blockDim.x + threadIdx.x;
    if (idx < KTOT * 1536) {
        int kq = idx / 1536, c = idx - kq * 1536;
        if (kq < 128) {
            const float* r = W_hh + (size_t)c * 512 + kq * 4;
            g_Wc[idx] = make_float4(r[0], r[1], r[2], r[3]);
        } else {
            const float* r = W_ih + (size_t)c * 192 + 128 + (kq - 128) * 4;
            g_Wc[idx] = make_float4(r[0], r[1], r[2], r[3]);
        }
    }
    if (idx < 32 * 1536) {
        int kq = idx / 1536, c = idx - kq * 1536;
        const float* r = W_ih + (size_t)c * 192 + kq * 4;
        g_Wy[idx] = make_float4(r[0], r[1], r[2], r[3]);
    }
    if (idx < 128 * 128) {
        int kq = idx >> 7, c = idx & 127;
        const float* src = (c < 64) ? (W_loc + c) : (W_scale + (c - 64));
        g_Woq[idx] = make_float4(src[(4 * kq + 0) * 64], src[(4 * kq + 1) * 64],
                                 src[(4 * kq + 2) * 64], src[(4 * kq + 3) * 64]);
    }
    if (idx < 512) {
        g_bR[idx]  = b_ih[idx] + b_hh[idx];
        g_bZ[idx]  = b_ih[512 + idx] + b_hh[512 + idx];
        g_bIN[idx] = b_ih[1024 + idx];
        g_bHN[idx] = b_hh[1024 + idx];
    }
    if (idx < 128) g_bO[idx] = (idx < 64) ? b_loc[idx] : b_scale[idx - 64];
}

// ---- packed f32x2 helpers (FFMA2 path; sm_103a only via PTX) ----
__device__ __forceinline__ void ffma2(u64& acc, u64 a, u64 b) {
    asm("fma.rn.f32x2 %0, %1, %2, %0;" : "+l"(acc) : "l"(a), "l"(b));
}
__device__ __forceinline__ u64 pack2(float lo, float hi) {
    u64 r; asm("mov.b64 %0, {%1, %2};" : "=l"(r) : "f"(lo), "f"(hi)); return r;
}
__device__ __forceinline__ void unpack2(u64 v, float& lo, float& hi) {
    asm("mov.b64 {%0, %1}, %2;" : "=f"(lo), "=f"(hi) : "l"(v));
}

#define DOT4(acc_, wv_, xv_) do { \
    (acc_) = fmaf((wv_).x, (xv_).x, (acc_)); \
    (acc_) = fmaf((wv_).y, (xv_).y, (acc_)); \
    (acc_) = fmaf((wv_).z, (xv_).z, (acc_)); \
    (acc_) = fmaf((wv_).w, (xv_).w, (acc_)); } while (0)

// one k step of the gate GEMM: weight component COMP of current float4s,
// NARR = accumulator array for the n-gate (aH for h-part, aN for l-part)
#define KSTEP(COMP, KOFF, NARR) do { \
    u64 w_r = pack2(cr.COMP, cr.COMP); \
    u64 w_z = pack2(cz.COMP, cz.COMP); \
    u64 w_n = pack2(cn.COMP, cn.COMP); \
    const ulonglong2* xr_ = (const ulonglong2*)(&xsp[4 * kq + (KOFF)][0]); \
    _Pragma("unroll") \
    for (int q = 0; q < 4; q++) { \
        ulonglong2 xq = xr_[q]; \
        ffma2(aR[2*q],   w_r, xq.x); ffma2(aR[2*q+1],   w_r, xq.y); \
        ffma2(aZ[2*q],   w_z, xq.x); ffma2(aZ[2*q+1],   w_z, xq.y); \
        ffma2(NARR[2*q], w_n, xq.x); ffma2(NARR[2*q+1], w_n, xq.y); \
    } } while (0)

__global__ void __launch_bounds__(THREADS, 1)
rnn_kernel(const float* __restrict__ y, const float* __restrict__ noise,
           float* __restrict__ out) {
    // xsp[k][p]: bit-packed float2 {row 2p, row 2p+1}; k<512 = h state, k>=512 = l state
    __shared__ u64   xsp[HID + XD][8];      // 36 KB
    __shared__ float4 ysA[32], ysB[32];     // 1 KB: y rows of the block's 2 b's
    __shared__ float  locsc[ROWS][128];     // 8 KB

    const int tid = threadIdx.x;
    const int blk = blockIdx.x;
    const int j = tid;                      // hidden unit owned in phase B

    for (int i = tid; i < (HID + XD) * 8; i += THREADS) ((u64*)xsp)[i] = 0ull;

    const float bR = g_bR[j], bZ = g_bZ[j], bIN = g_bIN[j], bHN = g_bHN[j];

    // phase C mapping: col cC in [0,128), rqC in [0,4) -> rows 4rqC..4rqC+3
    const int cC = tid & 127, rqC = tid >> 7;
    const float bO = g_bO[cC];
    // phase D mapping: warp per row
    const int rD = tid >> 5, laneD = tid & 31;
    const int sbD = (rD & 7) * NB + (2 * blk + (rD >> 3));

    const float4* __restrict__ wyp = g_Wy + j;
    const float4* __restrict__ wcp = g_Wc + j;

    for (int t = 0; t < NT; t++) {
        if (tid < 64) {
            const float4* yp = (const float4*)(y + (((size_t)(2 * blk + (tid >> 5))) * NT + t) * OBS);
            (tid < 32 ? ysA : ysB)[tid & 31] = yp[tid & 31];
        }
        __syncthreads();   // ys ready; prev step's state writes visible

        // ---- y-part (K=128), deduped: 2 distinct b rows, scalar dots ----
        float yR0 = 0.f, yR1 = 0.f, yZ0 = 0.f, yZ1 = 0.f, yN0 = 0.f, yN1 = 0.f;
#pragma unroll 1
        for (int kq = 0; kq < 32; kq++) {
            float4 wr = wyp[kq * 1536];
            float4 wz = wyp[kq * 1536 + 512];
            float4 wn = wyp[kq * 1536 + 1024];
            float4 x0 = ysA[kq];
            float4 x1 = ysB[kq];
            DOT4(yR0, wr, x0); DOT4(yZ0, wz, x0); DOT4(yN0, wn, x0);
            DOT4(yR1, wr, x1); DOT4(yZ1, wz, x1); DOT4(yN1, wn, x1);
        }

        // ---- gate GEMM over K = h(512) + l(64), packed row-pairs ----
        u64 aR[8], aZ[8], aN[8], aH[8];
#pragma unroll
        for (int p = 0; p < 8; p++) {
            float yr = (p < 4) ? yR0 : yR1;
            float yz = (p < 4) ? yZ0 : yZ1;
            float yn = (p < 4) ? yN0 : yN1;
            aR[p] = pack2(bR + yr, bR + yr);
            aZ[p] = pack2(bZ + yz, bZ + yz);
            aN[p] = pack2(bIN + yn, bIN + yn);
            aH[p] = pack2(bHN, bHN);
        }

        float4 cr = wcp[0], cz = wcp[512], cn = wcp[1024];
#pragma unroll 1
        for (int kq = 0; kq < 128; kq++) {            // h-part: n-gate -> aH
            int nx = kq + 1;
            float4 nr = wcp[nx * 1536], nz = wcp[nx * 1536 + 512], nn_ = wcp[nx * 1536 + 1024];
            KSTEP(x, 0, aH); KSTEP(y, 1, aH); KSTEP(z, 2, aH); KSTEP(w, 3, aH);
            cr = nr; cz = nz; cn = nn_;
        }
#pragma unroll 1
        for (int kq = 128; kq < KTOT; kq++) {         // l-part: n-gate -> aN
            int nx = (kq + 1 < KTOT) ? kq + 1 : kq;
            float4 nr = wcp[nx * 1536], nz = wcp[nx * 1536 + 512], nn_ = wcp[nx * 1536 + 1024];
            KSTEP(x, 0, aN); KSTEP(y, 1, aN); KSTEP(z, 2, aN); KSTEP(w, 3, aN);
            cr = nr; cz = nz; cn = nn_;
        }

        // ---- GRU update for unit j, 16 rows ----
        u64 hn2[8];
#pragma unroll
        for (int p = 0; p < 8; p++) {
            float r0, r1, z0, z1, n0, n1, hv0, hv1, g0, g1;
            unpack2(aR[p], r0, r1);
            unpack2(aZ[p], z0, z1);
            unpack2(aN[p], n0, n1);
            unpack2(aH[p], g0, g1);
            unpack2(xsp[j][p], hv0, hv1);
            float rg0 = 1.0f / (1.0f + __expf(-r0));
            float rg1 = 1.0f / (1.0f + __expf(-r1));
            float zg0 = 1.0f / (1.0f + __expf(-z0));
            float zg1 = 1.0f / (1.0f + __expf(-z1));
            float ng0 = tanhf(n0 + rg0 * g0);
            float ng1 = tanhf(n1 + rg1 * g1);
            hn2[p] = pack2((1.0f - zg0) * ng0 + zg0 * hv0,
                           (1.0f - zg1) * ng1 + zg1 * hv1);
        }
        __syncthreads();   // all reads of old state done
#pragma unroll
        for (int p = 0; p < 8; p++) xsp[j][p] = hn2[p];
        __syncthreads();   // new h visible

        // ---- loc/scale GEMM [16 x 128], K=512 ----
        {
            u64 aP0 = pack2(bO, bO), aP1 = pack2(bO, bO);
            const float4* __restrict__ wop = g_Woq + cC;
            float4 cw = wop[0];
#pragma unroll 1
            for (int kq = 0; kq < 128; kq++) {
                float4 nw = wop[((kq + 1) & 127) * 128];
#pragma unroll
                for (int kk = 0; kk < 4; kk++) {
                    float wc = (kk == 0) ? cw.x : (kk == 1) ? cw.y : (kk == 2) ? cw.z : cw.w;
                    u64 w2 = pack2(wc, wc);
                    ulonglong2 xq = ((const ulonglong2*)(&xsp[4 * kq + kk][0]))[rqC];
                    ffma2(aP0, w2, xq.x);
                    ffma2(aP1, w2, xq.y);
                }
                cw = nw;
            }
            float v0, v1, v2, v3;
            unpack2(aP0, v0, v1);
            unpack2(aP1, v2, v3);
            locsc[4 * rqC + 0][cC] = v0;
            locsc[4 * rqC + 1][cC] = v1;
            locsc[4 * rqC + 2][cC] = v2;
            locsc[4 * rqC + 3][cC] = v3;
        }
        __syncthreads();   // locsc ready

        // ---- rsample + entropy/logprob: warp per row ----
        {
            float ent = 0.f, lp = 0.f;
#pragma unroll
            for (int dd = 0; dd < 2; dd++) {
                int d = laneD + dd * 32;
                float loc = locsc[rD][d];
                float sa  = locsc[rD][64 + d];
                float scale = fmaxf(sa, 0.f) + log1pf(__expf(-fabsf(sa)));
                float eps = noise[(((size_t)t) * SB + sbD) * XD + d];
                float lnew = fmaf(scale, eps, loc);
                ((float*)&xsp[HID + d][rD >> 1])[rD & 1] = lnew;
                out[(((size_t)sbD) * NT + t) * XD + d] = lnew;
                float lsc = logf(scale);
                ent += 0.5f * (1.0f + LOG2PI) + lsc;
                lp  += -0.5f * eps * eps - lsc - 0.5f * LOG2PI;
            }
#pragma unroll
            for (int off = 16; off > 0; off >>= 1) {
                ent += __shfl_down_sync(0xffffffffu, ent, off);
                lp  += __shfl_down_sync(0xffffffffu, lp,  off);
            }
            if (laneD == 0) {
                out[67108864u + (size_t)sbD * NT + t] = ent;
                out[67108864u + 1048576u + (size_t)sbD * NT + t] = lp;
            }
        }
        // l writes fenced from next step's reads by the loop-top sync
    }
}

extern "C" void kernel_launch(void* const* d_in, const int* in_sizes, int n_in,
                              void* d_out, int out_size) {
    const float* y       = (const float*)d_in[0];
    const float* W_ih    = (const float*)d_in[1];
    const float* W_hh    = (const float*)d_in[2];
    const float* b_ih    = (const float*)d_in[3];
    const float* b_hh    = (const float*)d_in[4];
    const float* W_loc   = (const float*)d_in[5];
    const float* b_loc   = (const float*)d_in[6];
    const float* W_scale = (const float*)d_in[7];
    const float* b_scale = (const float*)d_in[8];
    const float* noise   = (const float*)d_in[9];
    float* out = (float*)d_out;

    prep_kernel<<<864, 256>>>(W_ih, W_hh, b_ih, b_hh, W_loc, b_loc, W_scale, b_scale);
    rnn_kernel<<<NBLK, THREADS>>>(y, noise, out);
}

// round 14
// speedup vs baseline: 1.0025x; 1.0025x over previous
#include <cuda_runtime.h>
#include <math.h>
#include <stdint.h>

// Problem constants
#define NS     8
#define NB     256
#define NT     512
#define OBS    128
#define HID    512
#define XD     64
#define SB     2048        // NS*NB
#define THREADS 512
#define NBLK   128
#define ROWS   16          // rows per block: 2 b's x 8 samples
#define KTOT   144         // (HID + XD)/4 float4-chunks of K

#define LOG2PI 1.8378770664093453f

typedef unsigned long long u64;

// ---- weights reorganized for streaming ----
// g_Wc[kq][c] : float4 over k; kq<128 -> W_hh (K=512), kq in [128,144) -> W_ih l-part (K=64)
//               c = gate*512 + j, gate 0=r,1=z,2=n
__device__ float4 g_Wc[KTOT * 1536];
// g_Wy[kq][c] : float4 over k (y-part of W_ih, K=128)
__device__ float4 g_Wy[32 * 1536];
// g_Woq[kq][c]: float4 over k (K=512), c in [0,128): loc(64) | scale(64)
__device__ float4 g_Woq[128 * 128];
__device__ float g_bR[512], g_bZ[512], g_bIN[512], g_bHN[512], g_bO[128];

__global__ void prep_kernel(const float* __restrict__ W_ih, const float* __restrict__ W_hh,
                            const float* __restrict__ b_ih, const float* __restrict__ b_hh,
                            const float* __restrict__ W_loc, const float* __restrict__ b_loc,
                            const float* __restrict__ W_scale, const float* __restrict__ b_scale) {
    int idx = blockIdx.x * blockDim.x + threadIdx.x;
    if (idx < KTOT * 1536) {
        int kq = idx / 1536, c = idx - kq * 1536;
        if (kq < 128) {
            const float* r = W_hh + (size_t)c * 512 + kq * 4;
            g_Wc[idx] = make_float4(r[0], r[1], r[2], r[3]);
        } else {
            const float* r = W_ih + (size_t)c * 192 + 128 + (kq - 128) * 4;
            g_Wc[idx] = make_float4(r[0], r[1], r[2], r[3]);
        }
    }
    if (idx < 32 * 1536) {
        int kq = idx / 1536, c = idx - kq * 1536;
        const float* r = W_ih + (size_t)c * 192 + kq * 4;
        g_Wy[idx] = make_float4(r[0], r[1], r[2], r[3]);
    }
    if (idx < 128 * 128) {
        int kq = idx >> 7, c = idx & 127;
        const float* src = (c < 64) ? (W_loc + c) : (W_scale + (c - 64));
        g_Woq[idx] = make_float4(src[(4 * kq + 0) * 64], src[(4 * kq + 1) * 64],
                                 src[(4 * kq + 2) * 64], src[(4 * kq + 3) * 64]);
    }
    if (idx < 512) {
        g_bR[idx]  = b_ih[idx] + b_hh[idx];
        g_bZ[idx]  = b_ih[512 + idx] + b_hh[512 + idx];
        g_bIN[idx] = b_ih[1024 + idx];
        g_bHN[idx] = b_hh[1024 + idx];
    }
    if (idx < 128) g_bO[idx] = (idx < 64) ? b_loc[idx] : b_scale[idx - 64];
}

// ---- packed f32x2 helpers (FFMA2 path; sm_103a only via PTX) ----
__device__ __forceinline__ void ffma2(u64& acc, u64 a, u64 b) {
    asm("fma.rn.f32x2 %0, %1, %2, %0;" : "+l"(acc) : "l"(a), "l"(b));
}
__device__ __forceinline__ u64 pack2(float lo, float hi) {
    u64 r; asm("mov.b64 %0, {%1, %2};" : "=l"(r) : "f"(lo), "f"(hi)); return r;
}
__device__ __forceinline__ void unpack2(u64 v, float& lo, float& hi) {
    asm("mov.b64 {%0, %1}, %2;" : "=f"(lo), "=f"(hi) : "l"(v));
}

#define DOT4(acc_, wv_, xv_) do { \
    (acc_) = fmaf((wv_).x, (xv_).x, (acc_)); \
    (acc_) = fmaf((wv_).y, (xv_).y, (acc_)); \
    (acc_) = fmaf((wv_).z, (xv_).z, (acc_)); \
    (acc_) = fmaf((wv_).w, (xv_).w, (acc_)); } while (0)

// one k step of the gate GEMM: weight component COMP of current float4s,
// NARR = accumulator array for the n-gate (aH for h-part, aN for l-part)
#define KSTEP(COMP, KOFF, NARR) do { \
    u64 w_r = pack2(cr.COMP, cr.COMP); \
    u64 w_z = pack2(cz.COMP, cz.COMP); \
    u64 w_n = pack2(cn.COMP, cn.COMP); \
    const ulonglong2* xr_ = (const ulonglong2*)(&xsp[4 * kq + (KOFF)][0]); \
    _Pragma("unroll") \
    for (int q = 0; q < 4; q++) { \
        ulonglong2 xq = xr_[q]; \
        ffma2(aR[2*q],   w_r, xq.x); ffma2(aR[2*q+1],   w_r, xq.y); \
        ffma2(aZ[2*q],   w_z, xq.x); ffma2(aZ[2*q+1],   w_z, xq.y); \
        ffma2(NARR[2*q], w_n, xq.x); ffma2(NARR[2*q+1], w_n, xq.y); \
    } } while (0)

__global__ void __launch_bounds__(THREADS, 1)
rnn_kernel(const float* __restrict__ y, const float* __restrict__ noise,
           float* __restrict__ out) {
    // xsp[k][p]: bit-packed float2 {row 2p, row 2p+1}; k<512 = h state, k>=512 = l state
    __shared__ u64   xsp[HID + XD][8];      // 36 KB
    __shared__ float4 ysA[32], ysB[32];     // 1 KB: y rows of the block's 2 b's
    __shared__ float  locsc[ROWS][128];     // 8 KB

    const int tid = threadIdx.x;
    const int blk = blockIdx.x;
    const int j = tid;                      // hidden unit owned in phase B

    for (int i = tid; i < (HID + XD) * 8; i += THREADS) ((u64*)xsp)[i] = 0ull;

    const float bR = g_bR[j], bZ = g_bZ[j], bIN = g_bIN[j], bHN = g_bHN[j];

    // phase C mapping: col cC in [0,128), rqC in [0,4) -> rows 4rqC..4rqC+3
    const int cC = tid & 127, rqC = tid >> 7;
    const float bO = g_bO[cC];
    // phase D mapping: warp per row
    const int rD = tid >> 5, laneD = tid & 31;
    const int sbD = (rD & 7) * NB + (2 * blk + (rD >> 3));

    const float4* __restrict__ wyp = g_Wy + j;
    const float4* __restrict__ wcp = g_Wc + j;

    for (int t = 0; t < NT; t++) {
        if (tid < 64) {
            const float4* yp = (const float4*)(y + (((size_t)(2 * blk + (tid >> 5))) * NT + t) * OBS);
            (tid < 32 ? ysA : ysB)[tid & 31] = yp[tid & 31];
        }
        __syncthreads();   // ys ready; prev step's state writes visible

        // ---- y-part (K=128), deduped: 2 distinct b rows, scalar dots ----
        float yR0 = 0.f, yR1 = 0.f, yZ0 = 0.f, yZ1 = 0.f, yN0 = 0.f, yN1 = 0.f;
#pragma unroll 1
        for (int kq = 0; kq < 32; kq++) {
            float4 wr = wyp[kq * 1536];
            float4 wz = wyp[kq * 1536 + 512];
            float4 wn = wyp[kq * 1536 + 1024];
            float4 x0 = ysA[kq];
            float4 x1 = ysB[kq];
            DOT4(yR0, wr, x0); DOT4(yZ0, wz, x0); DOT4(yN0, wn, x0);
            DOT4(yR1, wr, x1); DOT4(yZ1, wz, x1); DOT4(yN1, wn, x1);
        }

        // ---- gate GEMM over K = h(512) + l(64), packed row-pairs ----
        u64 aR[8], aZ[8], aN[8], aH[8];
#pragma unroll
        for (int p = 0; p < 8; p++) {
            float yr = (p < 4) ? yR0 : yR1;
            float yz = (p < 4) ? yZ0 : yZ1;
            float yn = (p < 4) ? yN0 : yN1;
            aR[p] = pack2(bR + yr, bR + yr);
            aZ[p] = pack2(bZ + yz, bZ + yz);
            aN[p] = pack2(bIN + yn, bIN + yn);
            aH[p] = pack2(bHN, bHN);
        }

        float4 cr = wcp[0], cz = wcp[512], cn = wcp[1024];
#pragma unroll 1
        for (int kq = 0; kq < 128; kq++) {            // h-part: n-gate -> aH
            int nx = kq + 1;
            float4 nr = wcp[nx * 1536], nz = wcp[nx * 1536 + 512], nn_ = wcp[nx * 1536 + 1024];
            KSTEP(x, 0, aH); KSTEP(y, 1, aH); KSTEP(z, 2, aH); KSTEP(w, 3, aH);
            cr = nr; cz = nz; cn = nn_;
        }
#pragma unroll 1
        for (int kq = 128; kq < KTOT; kq++) {         // l-part: n-gate -> aN
            int nx = (kq + 1 < KTOT) ? kq + 1 : kq;
            float4 nr = wcp[nx * 1536], nz = wcp[nx * 1536 + 512], nn_ = wcp[nx * 1536 + 1024];
            KSTEP(x, 0, aN); KSTEP(y, 1, aN); KSTEP(z, 2, aN); KSTEP(w, 3, aN);
            cr = nr; cz = nz; cn = nn_;
        }

        // ---- GRU update for unit j, 16 rows ----
        u64 hn2[8];
#pragma unroll
        for (int p = 0; p < 8; p++) {
            float r0, r1, z0, z1, n0, n1, hv0, hv1, g0, g1;
            unpack2(aR[p], r0, r1);
            unpack2(aZ[p], z0, z1);
            unpack2(aN[p], n0, n1);
            unpack2(aH[p], g0, g1);
            unpack2(xsp[j][p], hv0, hv1);
            float rg0 = 1.0f / (1.0f + __expf(-r0));
            float rg1 = 1.0f / (1.0f + __expf(-r1));
            float zg0 = 1.0f / (1.0f + __expf(-z0));
            float zg1 = 1.0f / (1.0f + __expf(-z1));
            float ng0 = tanhf(n0 + rg0 * g0);
            float ng1 = tanhf(n1 + rg1 * g1);
            hn2[p] = pack2((1.0f - zg0) * ng0 + zg0 * hv0,
                           (1.0f - zg1) * ng1 + zg1 * hv1);
        }
        __syncthreads();   // all reads of old state done
#pragma unroll
        for (int p = 0; p < 8; p++) xsp[j][p] = hn2[p];
        __syncthreads();   // new h visible

        // ---- loc/scale GEMM [16 x 128], K=512 ----
        {
            u64 aP0 = pack2(bO, bO), aP1 = pack2(bO, bO);
            const float4* __restrict__ wop = g_Woq + cC;
            float4 cw = wop[0];
#pragma unroll 1
            for (int kq = 0; kq < 128; kq++) {
                float4 nw = wop[((kq + 1) & 127) * 128];
#pragma unroll
                for (int kk = 0; kk < 4; kk++) {
                    float wc = (kk == 0) ? cw.x : (kk == 1) ? cw.y : (kk == 2) ? cw.z : cw.w;
                    u64 w2 = pack2(wc, wc);
                    ulonglong2 xq = ((const ulonglong2*)(&xsp[4 * kq + kk][0]))[rqC];
                    ffma2(aP0, w2, xq.x);
                    ffma2(aP1, w2, xq.y);
                }
                cw = nw;
            }
            float v0, v1, v2, v3;
            unpack2(aP0, v0, v1);
            unpack2(aP1, v2, v3);
            locsc[4 * rqC + 0][cC] = v0;
            locsc[4 * rqC + 1][cC] = v1;
            locsc[4 * rqC + 2][cC] = v2;
            locsc[4 * rqC + 3][cC] = v3;
        }
        __syncthreads();   // locsc ready

        // ---- rsample + entropy/logprob: warp per row ----
        {
            float ent = 0.f, lp = 0.f;
#pragma unroll
            for (int dd = 0; dd < 2; dd++) {
                int d = laneD + dd * 32;
                float loc = locsc[rD][d];
                float sa  = locsc[rD][64 + d];
                float scale = fmaxf(sa, 0.f) + log1pf(__expf(-fabsf(sa)));
                float eps = noise[(((size_t)t) * SB + sbD) * XD + d];
                float lnew = fmaf(scale, eps, loc);
                ((float*)&xsp[HID + d][rD >> 1])[rD & 1] = lnew;
                out[(((size_t)sbD) * NT + t) * XD + d] = lnew;
                float lsc = logf(scale);
                ent += 0.5f * (1.0f + LOG2PI) + lsc;
                lp  += -0.5f * eps * eps - lsc - 0.5f * LOG2PI;
            }
#pragma unroll
            for (int off = 16; off > 0; off >>= 1) {
                ent += __shfl_down_sync(0xffffffffu, ent, off);
                lp  += __shfl_down_sync(0xffffffffu, lp,  off);
            }
            if (laneD == 0) {
                out[67108864u + (size_t)sbD * NT + t] = ent;
                out[67108864u + 1048576u + (size_t)sbD * NT + t] = lp;
            }
        }
        // l writes fenced from next step's reads by the loop-top sync
    }
}

extern "C" void kernel_launch(void* const* d_in, const int* in_sizes, int n_in,
                              void* d_out, int out_size) {
    const float* y       = (const float*)d_in[0];
    const float* W_ih    = (const float*)d_in[1];
    const float* W_hh    = (const float*)d_in[2];
    const float* b_ih    = (const float*)d_in[3];
    const float* b_hh    = (const float*)d_in[4];
    const float* W_loc   = (const float*)d_in[5];
    const float* b_loc   = (const float*)d_in[6];
    const float* W_scale = (const float*)d_in[7];
    const float* b_scale = (const float*)d_in[8];
    const float* noise   = (const float*)d_in[9];
    float* out = (float*)d_out;

    prep_kernel<<<864, 256>>>(W_ih, W_hh, b_ih, b_hh, W_loc, b_loc, W_scale, b_scale);
    rnn_kernel<<<NBLK, THREADS>>>(y, noise, out);
}